// round 8
// baseline (speedup 1.0000x reference)
#include <cuda_runtime.h>
#include <cuda_fp16.h>
#include <cstdint>

#define BATCH 4096
#define DIM   512
#define GRID  128
#define NCELL (GRID*GRID)   // 16384
#define THR_REL 0.95f
#define LR_MAX 0.2f
#define LR_MIN 0.05f
#define CTX_MAX 2
#define CTX_MIN 0

// GEMM tiling: CTA 128x128, 8 warps (2x4), warp 64x32, k-slab 64, 4-stage pipe
#define KC 64
#define NS (DIM/KC)          // 8 slabs
#define APITCH 144           // bytes per smem row (64 fp16 = 128B data + 16B pad)
#define ARR (128*APITCH)     // 18432 bytes per smem array
#define STG (2*ARR)          // A, B = 36864
#define HDR 1536
#define SMEMT (HDR + 4*STG)  // 148992
#define NPART 128            // one partial set per (col-tile, row)

typedef unsigned long long u64;

// ---------------- device scratch ----------------
__device__ float   g_wnorm[NCELL];
__device__ u64     g_min[BATCH];
__device__ u64     g_cls[BATCH];
__device__ float   g_S0[NCELL * DIM];
__device__ float   g_cnt[NCELL];
__device__ float   g_sum;
__device__ float   g_lr;
__device__ int     g_ctx;
__device__ __half  g_xf[BATCH*DIM];
__device__ __half  g_wf[NCELL*DIM];
__device__ u64     g_part[(size_t)NPART * BATCH * 4];

// ---------------- PTX helpers (baseline ISA only) ----------------
__device__ __forceinline__ uint32_t smem_to_u32(const void* p) {
    uint32_t a;
    asm("{ .reg .u64 t; cvta.to.shared.u64 t, %1; cvt.u32.u64 %0, t; }" : "=r"(a) : "l"(p));
    return a;
}
#define CP_ASYNC16(d, s) \
    asm volatile("cp.async.cg.shared.global [%0], [%1], 16;" :: "r"(d), "l"(s) : "memory")
#define CP_COMMIT() asm volatile("cp.async.commit_group;" ::: "memory")
#define CP_WAIT(n)  asm volatile("cp.async.wait_group %0;" :: "n"(n) : "memory")

#define LDSM_X4(r, a) \
    asm volatile("ldmatrix.sync.aligned.m8n8.x4.shared.b16 {%0,%1,%2,%3}, [%4];" \
        : "=r"((r)[0]), "=r"((r)[1]), "=r"((r)[2]), "=r"((r)[3]) : "r"(a))
#define LDSM_X2(r, a) \
    asm volatile("ldmatrix.sync.aligned.m8n8.x2.shared.b16 {%0,%1}, [%2];" \
        : "=r"((r)[0]), "=r"((r)[1]) : "r"(a))
#define MMA_F16(dd, aa, bb) \
    asm volatile("mma.sync.aligned.m16n8k16.row.col.f32.f16.f16.f32 " \
        "{%0,%1,%2,%3}, {%4,%5,%6,%7}, {%8,%9}, {%0,%1,%2,%3};" \
        : "+f"((dd)[0]), "+f"((dd)[1]), "+f"((dd)[2]), "+f"((dd)[3]) \
        : "r"((aa)[0]), "r"((aa)[1]), "r"((aa)[2]), "r"((aa)[3]), \
          "r"((bb)[0]), "r"((bb)[1]))

__device__ __forceinline__ unsigned float_to_ordered(float f) {
    unsigned u = __float_as_uint(f);
    return (u & 0x80000000u) ? ~u : (u ^ 0x80000000u);
}
__device__ __forceinline__ void top2_ins(u64& m1, u64& m2, u64 v) {
    if (v < m1) { m2 = m1; m1 = v; } else if (v < m2) { m2 = v; }
}

// ---------------- schedule ----------------
__global__ void schedule_kernel(const int* __restrict__ epoch,
                                const int* __restrict__ max_epochs) {
    int e = epoch[0], me = max_epochs[0];
    float progress = (me > 0) ? (float)(me - e) / (float)me : 0.0f;
    progress = fminf(fmaxf(progress, 0.0f), 1.0f);
    float p2 = progress * progress;
    g_ctx = CTX_MIN + (int)(p2 * p2 * (float)(CTX_MAX - CTX_MIN));
    g_lr  = LR_MIN + progress * (LR_MAX - LR_MIN);
}

// ---------------- fp16 convert (X) ----------------
__global__ void tohalf_kernel(const float* __restrict__ src,
                              __half* __restrict__ dst, int n4) {
    int stride = gridDim.x * blockDim.x;
    for (int i = blockIdx.x * blockDim.x + threadIdx.x; i < n4; i += stride) {
        float4 v = ((const float4*)src)[i];
        union { __half h[4]; uint2 u; } H;
        H.h[0] = __float2half_rn(v.x);
        H.h[1] = __float2half_rn(v.y);
        H.h[2] = __float2half_rn(v.z);
        H.h[3] = __float2half_rn(v.w);
        ((uint2*)dst)[i] = H.u;
    }
}

// ---------------- fused W convert + w_norm ----------------
__global__ void wprep_kernel(const float* __restrict__ W,
                             __half* __restrict__ wf) {
    int warp = (blockIdx.x * blockDim.x + threadIdx.x) >> 5;
    int lane = threadIdx.x & 31;
    if (warp >= NCELL) return;
    const float4* row = (const float4*)(W + (size_t)warp * DIM);
    uint2* out = (uint2*)(wf + (size_t)warp * DIM);
    float s = 0.0f;
    #pragma unroll
    for (int i = 0; i < 4; i++) {
        float4 v = row[lane + 32 * i];
        s += v.x*v.x + v.y*v.y + v.z*v.z + v.w*v.w;
        union { __half h[4]; uint2 u; } H;
        H.h[0] = __float2half_rn(v.x);
        H.h[1] = __float2half_rn(v.y);
        H.h[2] = __float2half_rn(v.z);
        H.h[3] = __float2half_rn(v.w);
        out[lane + 32 * i] = H.u;
    }
    #pragma unroll
    for (int o = 16; o; o >>= 1) s += __shfl_xor_sync(0xFFFFFFFFu, s, o);
    if (lane == 0) g_wnorm[warp] = s;
}

// ---------------- fp16 mma.sync GEMM (f32 acc) + top-2 argmin + CTA combine ----------------
__global__ __launch_bounds__(256, 1)
void mma_argmin_kernel(const int* __restrict__ labels,
                       const int* __restrict__ cell_labels) {
    extern __shared__ char sm[];
    const uint32_t sbase = smem_to_u32(sm);
    const int tid = threadIdx.x;
    const int lane = tid & 31;
    const int wid = tid >> 5;
    const int rowBase = blockIdx.y * 128;
    const int colBase = blockIdx.x * 128;

    float* wn_s = (float*)sm;
    int*   cl_s = (int*)(sm + 512);
    int*   rl_s = (int*)(sm + 1024);
    if (tid < 128) {
        wn_s[tid] = g_wnorm[colBase + tid];
        cl_s[tid] = cell_labels[colBase + tid];
        rl_s[tid] = labels[rowBase + tid];
    }

    const int m0  = (wid >> 2) * 64;
    const int n0v = (wid & 3) * 32;

    float d[4][4][4];
    #pragma unroll
    for (int mi = 0; mi < 4; mi++)
        #pragma unroll
        for (int nj = 0; nj < 4; nj++)
            #pragma unroll
            for (int e = 0; e < 4; e++) d[mi][nj][e] = 0.0f;

    // lane-address components for ldmatrix
    const uint32_t aR = (uint32_t)(lane & 15);
    const uint32_t aK = (uint32_t)((lane >> 4) * 8);
    const uint32_t bR = (uint32_t)(lane & 7);
    const uint32_t bK = (uint32_t)(((lane >> 3) & 1) * 8);

    // stage loader via cp.async: A, B (8 x 16B per thread)
    auto load_stage = [&](int s) {
        const int k0 = s * KC;
        const uint32_t st = (uint32_t)HDR + (uint32_t)(s & 3) * STG;
        #pragma unroll
        for (int i = 0; i < 4; i++) {
            int slot = tid + i * 256;            // 0..1023
            int r = slot >> 3, q = slot & 7;
            uint32_t doff = sbase + st + (uint32_t)(r * APITCH + q * 16);
            CP_ASYNC16(doff,       &g_xf[(size_t)(rowBase + r) * DIM + k0 + q * 8]);
            CP_ASYNC16(doff + ARR, &g_wf[(size_t)(colBase + r) * DIM + k0 + q * 8]);
        }
    };

    load_stage(0); CP_COMMIT();
    load_stage(1); CP_COMMIT();
    load_stage(2); CP_COMMIT();

    for (int s = 0; s < NS; s++) {
        CP_WAIT(2);
        __syncthreads();
        const uint32_t st = sbase + (uint32_t)HDR + (uint32_t)(s & 3) * STG;
        #pragma unroll
        for (int ks = 0; ks < KC / 16; ks++) {
            uint32_t a[4][4], b[4][2];
            #pragma unroll
            for (int mi = 0; mi < 4; mi++) {
                uint32_t ad = st + (uint32_t)((m0 + mi * 16 + aR) * APITCH) +
                              (uint32_t)((ks * 16 + aK) * 2);
                LDSM_X4(a[mi], ad);
            }
            #pragma unroll
            for (int nj = 0; nj < 4; nj++) {
                uint32_t bd = st + ARR + (uint32_t)((n0v + nj * 8 + bR) * APITCH) +
                              (uint32_t)((ks * 16 + bK) * 2);
                LDSM_X2(b[nj], bd);
            }
            #pragma unroll
            for (int mi = 0; mi < 4; mi++)
                #pragma unroll
                for (int nj = 0; nj < 4; nj++)
                    MMA_F16(d[mi][nj], a[mi], b[nj]);
        }
        if (s + 3 < NS) { load_stage(s + 3); CP_COMMIT(); }
    }
    __syncthreads();   // all pipeline smem reads done; reuse for partials

    // ---- fused epilogue: per-row top-2 (plain + class-masked) ----
    u64* ps = (u64*)(sm + HDR);   // [row 0..127][wc 0..3][4] = 16KB
    const int g  = lane >> 2;
    const int t4 = lane & 3;
    const int wc = wid & 3;
    #pragma unroll
    for (int mi = 0; mi < 4; mi++) {
        const int lr0 = m0 + mi * 16 + g;
        const int lr1 = lr0 + 8;
        const int lab0 = rl_s[lr0];
        const int lab1 = rl_s[lr1];
        u64 m1a = ~0ull, m2a = ~0ull, c1a = ~0ull, c2a = ~0ull;
        u64 m1b = ~0ull, m2b = ~0ull, c1b = ~0ull, c2b = ~0ull;
        #pragma unroll
        for (int nj = 0; nj < 4; nj++) {
            #pragma unroll
            for (int e = 0; e < 2; e++) {
                int lc = n0v + nj * 8 + t4 * 2 + e;
                float wn = wn_s[lc];
                int   cl = cl_s[lc];
                unsigned col = (unsigned)(colBase + lc);
                float s0 = fmaf(-2.0f, d[mi][nj][e], wn);
                u64 p0 = ((u64)float_to_ordered(s0) << 32) | col;
                top2_ins(m1a, m2a, p0);
                if (cl == lab0) top2_ins(c1a, c2a, p0);
                float s1 = fmaf(-2.0f, d[mi][nj][2 + e], wn);
                u64 p1 = ((u64)float_to_ordered(s1) << 32) | col;
                top2_ins(m1b, m2b, p1);
                if (cl == lab1) top2_ins(c1b, c2b, p1);
            }
        }
        #pragma unroll
        for (int o = 1; o <= 2; o <<= 1) {
            u64 q1, q2;
            q1 = __shfl_xor_sync(0xFFFFFFFFu, m1a, o); q2 = __shfl_xor_sync(0xFFFFFFFFu, m2a, o);
            top2_ins(m1a, m2a, q1); top2_ins(m1a, m2a, q2);
            q1 = __shfl_xor_sync(0xFFFFFFFFu, c1a, o); q2 = __shfl_xor_sync(0xFFFFFFFFu, c2a, o);
            top2_ins(c1a, c2a, q1); top2_ins(c1a, c2a, q2);
            q1 = __shfl_xor_sync(0xFFFFFFFFu, m1b, o); q2 = __shfl_xor_sync(0xFFFFFFFFu, m2b, o);
            top2_ins(m1b, m2b, q1); top2_ins(m1b, m2b, q2);
            q1 = __shfl_xor_sync(0xFFFFFFFFu, c1b, o); q2 = __shfl_xor_sync(0xFFFFFFFFu, c2b, o);
            top2_ins(c1b, c2b, q1); top2_ins(c1b, c2b, q2);
        }
        if (t4 == 0) {
            u64* p0 = &ps[((size_t)lr0 * 4 + wc) * 4];
            p0[0] = m1a; p0[1] = m2a; p0[2] = c1a; p0[3] = c2a;
            u64* p1 = &ps[((size_t)lr1 * 4 + wc) * 4];
            p1[0] = m1b; p1[1] = m2b; p1[2] = c1b; p1[3] = c2b;
        }
    }
    __syncthreads();

    // ---- CTA-level combine: one partial set per row ----
    if (tid < 128) {
        u64 M1 = ~0ull, M2 = ~0ull, C1 = ~0ull, C2 = ~0ull;
        #pragma unroll
        for (int w = 0; w < 4; w++) {
            const u64* p = &ps[((size_t)tid * 4 + w) * 4];
            top2_ins(M1, M2, p[0]); top2_ins(M1, M2, p[1]);
            top2_ins(C1, C2, p[2]); top2_ins(C1, C2, p[3]);
        }
        size_t pb = ((size_t)blockIdx.x * BATCH + (size_t)(rowBase + tid)) * 4;
        g_part[pb+0] = M1; g_part[pb+1] = M2; g_part[pb+2] = C1; g_part[pb+3] = C2;
    }
}

// ---------------- merge partials + exact fp32 rescore ----------------
__device__ __forceinline__ float warp_dot(const float* __restrict__ x,
                                          const float* __restrict__ w, int lane) {
    const float4* xv = (const float4*)x + lane * 4;
    const float4* wv = (const float4*)w + lane * 4;
    float acc = 0.0f;
    #pragma unroll
    for (int q = 0; q < 4; q++) {
        float4 a = xv[q], b = wv[q];
        acc = fmaf(a.x, b.x, acc); acc = fmaf(a.y, b.y, acc);
        acc = fmaf(a.z, b.z, acc); acc = fmaf(a.w, b.w, acc);
    }
    #pragma unroll
    for (int o = 16; o; o >>= 1) acc += __shfl_xor_sync(0xFFFFFFFFu, acc, o);
    return acc;
}

__global__ void reduce_rescore_kernel(const float* __restrict__ X,
                                      const float* __restrict__ W) {
    const int lane = threadIdx.x & 31;
    const int row = blockIdx.x * 8 + (threadIdx.x >> 5);

    u64 m1 = ~0ull, m2 = ~0ull, c1 = ~0ull, c2 = ~0ull;
    #pragma unroll
    for (int t = 0; t < NPART / 32; t++) {
        int tile = lane + t * 32;
        const ulonglong2* p = (const ulonglong2*)&g_part[((size_t)tile * BATCH + row) * 4];
        ulonglong2 a = p[0], b = p[1];
        top2_ins(m1, m2, a.x); top2_ins(m1, m2, a.y);
        top2_ins(c1, c2, b.x); top2_ins(c1, c2, b.y);
    }
    #pragma unroll
    for (int o = 16; o; o >>= 1) {
        u64 q1 = __shfl_xor_sync(0xFFFFFFFFu, m1, o);
        u64 q2 = __shfl_xor_sync(0xFFFFFFFFu, m2, o);
        top2_ins(m1, m2, q1); top2_ins(m1, m2, q2);
        q1 = __shfl_xor_sync(0xFFFFFFFFu, c1, o);
        q2 = __shfl_xor_sync(0xFFFFFFFFu, c2, o);
        top2_ins(c1, c2, q1); top2_ins(c1, c2, q2);
    }

    const float* xr = X + (size_t)row * DIM;

    unsigned i1 = (unsigned)m1, i2 = (unsigned)m2;
    float s1 = g_wnorm[i1] - 2.0f * warp_dot(xr, W + (size_t)i1 * DIM, lane);
    float s2 = g_wnorm[i2] - 2.0f * warp_dot(xr, W + (size_t)i2 * DIM, lane);
    unsigned best = i1; float sb = s1;
    if (s2 < sb || (s2 == sb && i2 < best)) { best = i2; sb = s2; }
    if (lane == 0)
        g_min[row] = ((u64)float_to_ordered(sb) << 32) | best;

    u64 outc = ~0ull;
    if (c1 != ~0ull) {
        unsigned j1 = (unsigned)c1;
        float t1 = g_wnorm[j1] - 2.0f * warp_dot(xr, W + (size_t)j1 * DIM, lane);
        unsigned bc = j1; float tb = t1;
        if (c2 != ~0ull) {
            unsigned j2 = (unsigned)c2;
            float t2 = g_wnorm[j2] - 2.0f * warp_dot(xr, W + (size_t)j2 * DIM, lane);
            if (t2 < tb || (t2 == tb && j2 < bc)) { bc = j2; tb = t2; }
        }
        outc = ((u64)float_to_ordered(tb) << 32) | bc;
    }
    if (lane == 0) g_cls[row] = outc;
}

// ---------------- per-sample: som_errors, min_dist sum, BMU scatter ----------------
__global__ void persample_kernel(const float* __restrict__ X,
                                 const float* __restrict__ W,
                                 const float* __restrict__ cell_rel,
                                 float* __restrict__ out_err) {
    const int i = blockIdx.x;
    const int t = threadIdx.x;
    float4 x = *(const float4*)&X[(size_t)i * DIM + t * 4];

    float s = x.x*x.x + x.y*x.y + x.z*x.z + x.w*x.w;
    #pragma unroll
    for (int o = 16; o; o >>= 1) s += __shfl_xor_sync(0xFFFFFFFFu, s, o);
    __shared__ float red[4];
    if ((t & 31) == 0) red[t >> 5] = s;
    __syncthreads();
    float xn = red[0] + red[1] + red[2] + red[3];

    u64 pm = g_min[i];
    u64 pc = g_cls[i];
    unsigned bmu = (unsigned)pm;
    unsigned ub  = (unsigned)(pm >> 32);
    ub = (ub & 0x80000000u) ? (ub ^ 0x80000000u) : ~ub;
    float smin = __uint_as_float(ub);
    if (t == 0) atomicAdd(&g_sum, fmaxf(xn + smin, 0.0f));

    unsigned cls = (unsigned)pc;
    if (cls >= (unsigned)NCELL) cls = 0;

    float rel = cell_rel[cls] / 100.0f;
    float fac = (rel >= THR_REL) ? 0.01f * rel : 0.0f;
    float4 w = *(const float4*)&W[(size_t)cls * DIM + t * 4];
    float4 e;
    e.x = fac * (w.x - x.x);
    e.y = fac * (w.y - x.y);
    e.z = fac * (w.z - x.z);
    e.w = fac * (w.w - x.w);
    *(float4*)&out_err[(size_t)i * DIM + t * 4] = e;

    int bx = (int)(bmu / GRID), by = (int)(bmu % GRID);
    int center = by * GRID + bx;
    float* dst = &g_S0[(size_t)center * DIM + t * 4];
    atomicAdd(dst + 0, x.x);
    atomicAdd(dst + 1, x.y);
    atomicAdd(dst + 2, x.z);
    atomicAdd(dst + 3, x.w);
    if (t == 0) atomicAdd(&g_cnt[center], 1.0f);
}

// ---------------- stencil conv + SOM update ----------------
__global__ void update_kernel(const float* __restrict__ som,
                              float* __restrict__ out_som) {
    const int cell = blockIdx.x;
    const int a = cell >> 7, c = cell & 127;
    const int t = threadIdx.x;
    const int ctx = g_ctx;
    const float lr = g_lr;
    const bool flag = (g_sum / (float)BATCH) > 1e-4f;

    float denom = 0.0f;
    float4 num = make_float4(0.f, 0.f, 0.f, 0.f);
    for (int dy = -ctx; dy <= ctx; dy++) {
        int aa = a + dy;
        if (aa < 0 || aa >= GRID) continue;
        for (int dx = -ctx; dx <= ctx; dx++) {
            int cc = c + dx;
            if (cc < 0 || cc >= GRID) continue;
            int ch = max(abs(dy), abs(dx));
            float w = ldexpf(lr, -ch);
            int nb = aa * GRID + cc;
            denom += w * g_cnt[nb];
            float4 sv = *(const float4*)&g_S0[(size_t)nb * DIM + t * 4];
            num.x += w * sv.x; num.y += w * sv.y;
            num.z += w * sv.z; num.w += w * sv.w;
        }
    }
    float4 smv = *(const float4*)&som[(size_t)cell * DIM + t * 4];
    float4 o;
    if (flag) {
        o.x = smv.x + num.x - smv.x * denom;
        o.y = smv.y + num.y - smv.y * denom;
        o.z = smv.z + num.z - smv.z * denom;
        o.w = smv.w + num.w - smv.w * denom;
    } else {
        o = smv;
    }
    *(float4*)&out_som[(size_t)cell * DIM + t * 4] = o;
}

// ---------------- launch ----------------
extern "C" void kernel_launch(void* const* d_in, const int* in_sizes, int n_in,
                              void* d_out, int out_size) {
    const float* X          = (const float*)d_in[0];
    const int*   labels     = (const int*)  d_in[1];
    const float* som        = (const float*)d_in[2];
    const int*   cell_lab   = (const int*)  d_in[3];
    const float* cell_rel   = (const float*)d_in[4];
    const int*   epoch      = (const int*)  d_in[5];
    const int*   max_epochs = (const int*)  d_in[6];
    (void)in_sizes; (void)n_in; (void)out_size;

    float* out_err = (float*)d_out;
    float* out_som = (float*)d_out + (size_t)BATCH * DIM;

    cudaFuncSetAttribute(mma_argmin_kernel,
                         cudaFuncAttributeMaxDynamicSharedMemorySize, SMEMT);

    void *pS0, *pCnt, *pSum;
    cudaGetSymbolAddress(&pS0,  g_S0);
    cudaGetSymbolAddress(&pCnt, g_cnt);
    cudaGetSymbolAddress(&pSum, g_sum);
    cudaMemsetAsync(pS0,  0, sizeof(float) * (size_t)NCELL * DIM);
    cudaMemsetAsync(pCnt, 0, sizeof(float) * NCELL);
    cudaMemsetAsync(pSum, 0, sizeof(float));

    void *pxf, *pwf;
    cudaGetSymbolAddress(&pxf, g_xf);
    cudaGetSymbolAddress(&pwf, g_wf);

    schedule_kernel<<<1, 1>>>(epoch, max_epochs);
    tohalf_kernel<<<1024, 256>>>(X, (__half*)pxf, BATCH * DIM / 4);
    wprep_kernel<<<NCELL / 8, 256>>>(som, (__half*)pwf);
    mma_argmin_kernel<<<dim3(NCELL / 128, BATCH / 128), 256, SMEMT>>>(labels, cell_lab);
    reduce_rescore_kernel<<<BATCH / 8, 256>>>(X, som);
    persample_kernel<<<BATCH, 128>>>(X, som, cell_rel, out_err);
    update_kernel<<<NCELL, 128>>>(som, out_som);
}

// round 10
// speedup vs baseline: 1.0301x; 1.0301x over previous
#include <cuda_runtime.h>
#include <cuda_fp16.h>
#include <cstdint>

#define BATCH 4096
#define DIM   512
#define GRID  128
#define NCELL (GRID*GRID)   // 16384
#define THR_REL 0.95f
#define LR_MAX 0.2f
#define LR_MIN 0.05f
#define CTX_MAX 2
#define CTX_MIN 0

// GEMM tiling: CTA 128x128, 16 warps (4x4), warp 32x32, k-slab 64, 4-stage pipe
#define KC 64
#define NS (DIM/KC)          // 8 slabs
#define APITCH 144           // bytes per smem row (64 fp16 = 128B data + 16B pad)
#define ARR (128*APITCH)     // 18432 bytes per smem array
#define STG (2*ARR)          // A, B = 36864
#define HDR 1536
#define SMEMT (HDR + 4*STG)  // 148992
#define NPART 128            // one partial set per (col-tile, row)

typedef unsigned long long u64;

// ---------------- device scratch ----------------
__device__ float   g_wnorm[NCELL];
__device__ u64     g_min[BATCH];
__device__ u64     g_cls[BATCH];
__device__ float   g_S0[NCELL * DIM];
__device__ float   g_cnt[NCELL];
__device__ float   g_sum;
__device__ float   g_lr;
__device__ int     g_ctx;
__device__ __half  g_xf[BATCH*DIM];
__device__ __half  g_wf[NCELL*DIM];
__device__ u64     g_part[(size_t)NPART * BATCH * 4];

// ---------------- PTX helpers (baseline ISA only) ----------------
__device__ __forceinline__ uint32_t smem_to_u32(const void* p) {
    uint32_t a;
    asm("{ .reg .u64 t; cvta.to.shared.u64 t, %1; cvt.u32.u64 %0, t; }" : "=r"(a) : "l"(p));
    return a;
}
#define CP_ASYNC16(d, s) \
    asm volatile("cp.async.cg.shared.global [%0], [%1], 16;" :: "r"(d), "l"(s) : "memory")
#define CP_COMMIT() asm volatile("cp.async.commit_group;" ::: "memory")
#define CP_WAIT(n)  asm volatile("cp.async.wait_group %0;" :: "n"(n) : "memory")

#define LDSM_X4(r, a) \
    asm volatile("ldmatrix.sync.aligned.m8n8.x4.shared.b16 {%0,%1,%2,%3}, [%4];" \
        : "=r"((r)[0]), "=r"((r)[1]), "=r"((r)[2]), "=r"((r)[3]) : "r"(a))
#define MMA_F16(dd, aa, bb) \
    asm volatile("mma.sync.aligned.m16n8k16.row.col.f32.f16.f16.f32 " \
        "{%0,%1,%2,%3}, {%4,%5,%6,%7}, {%8,%9}, {%0,%1,%2,%3};" \
        : "+f"((dd)[0]), "+f"((dd)[1]), "+f"((dd)[2]), "+f"((dd)[3]) \
        : "r"((aa)[0]), "r"((aa)[1]), "r"((aa)[2]), "r"((aa)[3]), \
          "r"((bb)[0]), "r"((bb)[1]))

__device__ __forceinline__ unsigned float_to_ordered(float f) {
    unsigned u = __float_as_uint(f);
    return (u & 0x80000000u) ? ~u : (u ^ 0x80000000u);
}
__device__ __forceinline__ void top2_ins(u64& m1, u64& m2, u64 v) {
    if (v < m1) { m2 = m1; m1 = v; } else if (v < m2) { m2 = v; }
}

// ---------------- schedule ----------------
__global__ void schedule_kernel(const int* __restrict__ epoch,
                                const int* __restrict__ max_epochs) {
    int e = epoch[0], me = max_epochs[0];
    float progress = (me > 0) ? (float)(me - e) / (float)me : 0.0f;
    progress = fminf(fmaxf(progress, 0.0f), 1.0f);
    float p2 = progress * progress;
    g_ctx = CTX_MIN + (int)(p2 * p2 * (float)(CTX_MAX - CTX_MIN));
    g_lr  = LR_MIN + progress * (LR_MAX - LR_MIN);
}

// ---------------- fp16 convert (X) ----------------
__global__ void tohalf_kernel(const float* __restrict__ src,
                              __half* __restrict__ dst, int n4) {
    int stride = gridDim.x * blockDim.x;
    for (int i = blockIdx.x * blockDim.x + threadIdx.x; i < n4; i += stride) {
        float4 v = ((const float4*)src)[i];
        union { __half h[4]; uint2 u; } H;
        H.h[0] = __float2half_rn(v.x);
        H.h[1] = __float2half_rn(v.y);
        H.h[2] = __float2half_rn(v.z);
        H.h[3] = __float2half_rn(v.w);
        ((uint2*)dst)[i] = H.u;
    }
}

// ---------------- fused W convert + w_norm ----------------
__global__ void wprep_kernel(const float* __restrict__ W,
                             __half* __restrict__ wf) {
    int warp = (blockIdx.x * blockDim.x + threadIdx.x) >> 5;
    int lane = threadIdx.x & 31;
    if (warp >= NCELL) return;
    const float4* row = (const float4*)(W + (size_t)warp * DIM);
    uint2* out = (uint2*)(wf + (size_t)warp * DIM);
    float s = 0.0f;
    #pragma unroll
    for (int i = 0; i < 4; i++) {
        float4 v = row[lane + 32 * i];
        s += v.x*v.x + v.y*v.y + v.z*v.z + v.w*v.w;
        union { __half h[4]; uint2 u; } H;
        H.h[0] = __float2half_rn(v.x);
        H.h[1] = __float2half_rn(v.y);
        H.h[2] = __float2half_rn(v.z);
        H.h[3] = __float2half_rn(v.w);
        out[lane + 32 * i] = H.u;
    }
    #pragma unroll
    for (int o = 16; o; o >>= 1) s += __shfl_xor_sync(0xFFFFFFFFu, s, o);
    if (lane == 0) g_wnorm[warp] = s;
}

// ---------------- fp16 mma.sync GEMM (f32 acc), 16 warps, + top-2 argmin ----------------
__global__ __launch_bounds__(512, 1)
void mma_argmin_kernel(const int* __restrict__ labels,
                       const int* __restrict__ cell_labels) {
    extern __shared__ char sm[];
    const uint32_t sbase = smem_to_u32(sm);
    const int tid = threadIdx.x;
    const int lane = tid & 31;
    const int wid = tid >> 5;
    const int rowBase = blockIdx.y * 128;
    const int colBase = blockIdx.x * 128;

    float* wn_s = (float*)sm;
    int*   cl_s = (int*)(sm + 512);
    int*   rl_s = (int*)(sm + 1024);
    if (tid < 128) {
        wn_s[tid] = g_wnorm[colBase + tid];
        cl_s[tid] = cell_labels[colBase + tid];
        rl_s[tid] = labels[rowBase + tid];
    }

    const int wm = wid >> 2;          // 0..3  (M group)
    const int wn = wid & 3;           // 0..3  (N group)
    const int m0  = wm * 32;
    const int n0v = wn * 32;

    float d[2][4][4];
    #pragma unroll
    for (int mi = 0; mi < 2; mi++)
        #pragma unroll
        for (int nj = 0; nj < 4; nj++)
            #pragma unroll
            for (int e = 0; e < 4; e++) d[mi][nj][e] = 0.0f;

    // ldmatrix lane-address components
    // A x4 (m16k16): lanes 0-15 rows, lanes 16-31 same rows k+8
    const uint32_t aOff = (uint32_t)((m0 + (lane & 15)) * APITCH + ((lane >> 4) * 8) * 2);
    // B x4 (two n8k16 tiles): m0,m1 = n rows 0-7 k halves; m2,m3 = n rows 8-15 k halves
    const uint32_t bOff = (uint32_t)((n0v + ((lane >> 4) & 1) * 8 + (lane & 7)) * APITCH +
                                     (((lane >> 3) & 1) * 8) * 2);

    // stage loader via cp.async: A, B (4 x 16B per thread)
    auto load_stage = [&](int s) {
        const int k0 = s * KC;
        const uint32_t st = (uint32_t)HDR + (uint32_t)(s & 3) * STG;
        #pragma unroll
        for (int i = 0; i < 2; i++) {
            int slot = tid + i * 512;            // 0..1023
            int r = slot >> 3, q = slot & 7;
            uint32_t doff = sbase + st + (uint32_t)(r * APITCH + q * 16);
            CP_ASYNC16(doff,       &g_xf[(size_t)(rowBase + r) * DIM + k0 + q * 8]);
            CP_ASYNC16(doff + ARR, &g_wf[(size_t)(colBase + r) * DIM + k0 + q * 8]);
        }
    };

    load_stage(0); CP_COMMIT();
    load_stage(1); CP_COMMIT();
    load_stage(2); CP_COMMIT();

    for (int s = 0; s < NS; s++) {
        CP_WAIT(2);
        __syncthreads();
        const uint32_t st = sbase + (uint32_t)HDR + (uint32_t)(s & 3) * STG;
        const uint32_t aBase = st + aOff;
        const uint32_t bBase = st + ARR + bOff;
        #pragma unroll
        for (int ks = 0; ks < KC / 16; ks++) {
            uint32_t a[2][4], bq[2][4];
            #pragma unroll
            for (int mi = 0; mi < 2; mi++)
                LDSM_X4(a[mi], aBase + (uint32_t)(mi * 16 * APITCH + ks * 32));
            #pragma unroll
            for (int p = 0; p < 2; p++)
                LDSM_X4(bq[p], bBase + (uint32_t)(p * 16 * APITCH + ks * 32));
            #pragma unroll
            for (int mi = 0; mi < 2; mi++)
                #pragma unroll
                for (int nj = 0; nj < 4; nj++)
                    MMA_F16(d[mi][nj], a[mi], &bq[nj >> 1][(nj & 1) * 2]);
        }
        // prefetch into stage (s+3)&3 == (s-1)&3: drained by the barrier above
        if (s + 3 < NS) { load_stage(s + 3); CP_COMMIT(); }
    }
    __syncthreads();   // pipeline smem reads done; reuse for partials

    // ---- fused epilogue: per-row top-2 (plain + class-masked) ----
    u64* ps = (u64*)(sm + HDR);   // [row 0..127][wn 0..3][4] = 16KB
    const int g  = lane >> 2;
    const int t4 = lane & 3;
    #pragma unroll
    for (int mi = 0; mi < 2; mi++) {
        const int lr0 = m0 + mi * 16 + g;
        const int lr1 = lr0 + 8;
        const int lab0 = rl_s[lr0];
        const int lab1 = rl_s[lr1];
        u64 m1a = ~0ull, m2a = ~0ull, c1a = ~0ull, c2a = ~0ull;
        u64 m1b = ~0ull, m2b = ~0ull, c1b = ~0ull, c2b = ~0ull;
        #pragma unroll
        for (int nj = 0; nj < 4; nj++) {
            #pragma unroll
            for (int e = 0; e < 2; e++) {
                int lc = n0v + nj * 8 + t4 * 2 + e;
                float wnv = wn_s[lc];
                int   cl  = cl_s[lc];
                unsigned col = (unsigned)(colBase + lc);
                float s0 = fmaf(-2.0f, d[mi][nj][e], wnv);
                u64 p0 = ((u64)float_to_ordered(s0) << 32) | col;
                top2_ins(m1a, m2a, p0);
                if (cl == lab0) top2_ins(c1a, c2a, p0);
                float s1 = fmaf(-2.0f, d[mi][nj][2 + e], wnv);
                u64 p1 = ((u64)float_to_ordered(s1) << 32) | col;
                top2_ins(m1b, m2b, p1);
                if (cl == lab1) top2_ins(c1b, c2b, p1);
            }
        }
        #pragma unroll
        for (int o = 1; o <= 2; o <<= 1) {
            u64 q1, q2;
            q1 = __shfl_xor_sync(0xFFFFFFFFu, m1a, o); q2 = __shfl_xor_sync(0xFFFFFFFFu, m2a, o);
            top2_ins(m1a, m2a, q1); top2_ins(m1a, m2a, q2);
            q1 = __shfl_xor_sync(0xFFFFFFFFu, c1a, o); q2 = __shfl_xor_sync(0xFFFFFFFFu, c2a, o);
            top2_ins(c1a, c2a, q1); top2_ins(c1a, c2a, q2);
            q1 = __shfl_xor_sync(0xFFFFFFFFu, m1b, o); q2 = __shfl_xor_sync(0xFFFFFFFFu, m2b, o);
            top2_ins(m1b, m2b, q1); top2_ins(m1b, m2b, q2);
            q1 = __shfl_xor_sync(0xFFFFFFFFu, c1b, o); q2 = __shfl_xor_sync(0xFFFFFFFFu, c2b, o);
            top2_ins(c1b, c2b, q1); top2_ins(c1b, c2b, q2);
        }
        if (t4 == 0) {
            u64* p0 = &ps[((size_t)lr0 * 4 + wn) * 4];
            p0[0] = m1a; p0[1] = m2a; p0[2] = c1a; p0[3] = c2a;
            u64* p1 = &ps[((size_t)lr1 * 4 + wn) * 4];
            p1[0] = m1b; p1[1] = m2b; p1[2] = c1b; p1[3] = c2b;
        }
    }
    __syncthreads();

    // ---- CTA-level combine: one partial set per row ----
    if (tid < 128) {
        u64 M1 = ~0ull, M2 = ~0ull, C1 = ~0ull, C2 = ~0ull;
        #pragma unroll
        for (int w = 0; w < 4; w++) {
            const u64* p = &ps[((size_t)tid * 4 + w) * 4];
            top2_ins(M1, M2, p[0]); top2_ins(M1, M2, p[1]);
            top2_ins(C1, C2, p[2]); top2_ins(C1, C2, p[3]);
        }
        size_t pb = ((size_t)blockIdx.x * BATCH + (size_t)(rowBase + tid)) * 4;
        g_part[pb+0] = M1; g_part[pb+1] = M2; g_part[pb+2] = C1; g_part[pb+3] = C2;
    }
}

// ---------------- merge partials + exact fp32 rescore ----------------
__device__ __forceinline__ float warp_dot(const float* __restrict__ x,
                                          const float* __restrict__ w, int lane) {
    const float4* xv = (const float4*)x + lane * 4;
    const float4* wv = (const float4*)w + lane * 4;
    float acc = 0.0f;
    #pragma unroll
    for (int q = 0; q < 4; q++) {
        float4 a = xv[q], b = wv[q];
        acc = fmaf(a.x, b.x, acc); acc = fmaf(a.y, b.y, acc);
        acc = fmaf(a.z, b.z, acc); acc = fmaf(a.w, b.w, acc);
    }
    #pragma unroll
    for (int o = 16; o; o >>= 1) acc += __shfl_xor_sync(0xFFFFFFFFu, acc, o);
    return acc;
}

__global__ void reduce_rescore_kernel(const float* __restrict__ X,
                                      const float* __restrict__ W) {
    const int lane = threadIdx.x & 31;
    const int row = blockIdx.x * 8 + (threadIdx.x >> 5);

    u64 m1 = ~0ull, m2 = ~0ull, c1 = ~0ull, c2 = ~0ull;
    #pragma unroll
    for (int t = 0; t < NPART / 32; t++) {
        int tile = lane + t * 32;
        const ulonglong2* p = (const ulonglong2*)&g_part[((size_t)tile * BATCH + row) * 4];
        ulonglong2 a = p[0], b = p[1];
        top2_ins(m1, m2, a.x); top2_ins(m1, m2, a.y);
        top2_ins(c1, c2, b.x); top2_ins(c1, c2, b.y);
    }
    #pragma unroll
    for (int o = 16; o; o >>= 1) {
        u64 q1 = __shfl_xor_sync(0xFFFFFFFFu, m1, o);
        u64 q2 = __shfl_xor_sync(0xFFFFFFFFu, m2, o);
        top2_ins(m1, m2, q1); top2_ins(m1, m2, q2);
        q1 = __shfl_xor_sync(0xFFFFFFFFu, c1, o);
        q2 = __shfl_xor_sync(0xFFFFFFFFu, c2, o);
        top2_ins(c1, c2, q1); top2_ins(c1, c2, q2);
    }

    const float* xr = X + (size_t)row * DIM;

    unsigned i1 = (unsigned)m1, i2 = (unsigned)m2;
    float s1 = g_wnorm[i1] - 2.0f * warp_dot(xr, W + (size_t)i1 * DIM, lane);
    float s2 = g_wnorm[i2] - 2.0f * warp_dot(xr, W + (size_t)i2 * DIM, lane);
    unsigned best = i1; float sb = s1;
    if (s2 < sb || (s2 == sb && i2 < best)) { best = i2; sb = s2; }
    if (lane == 0)
        g_min[row] = ((u64)float_to_ordered(sb) << 32) | best;

    u64 outc = ~0ull;
    if (c1 != ~0ull) {
        unsigned j1 = (unsigned)c1;
        float t1 = g_wnorm[j1] - 2.0f * warp_dot(xr, W + (size_t)j1 * DIM, lane);
        unsigned bc = j1; float tb = t1;
        if (c2 != ~0ull) {
            unsigned j2 = (unsigned)c2;
            float t2 = g_wnorm[j2] - 2.0f * warp_dot(xr, W + (size_t)j2 * DIM, lane);
            if (t2 < tb || (t2 == tb && j2 < bc)) { bc = j2; tb = t2; }
        }
        outc = ((u64)float_to_ordered(tb) << 32) | bc;
    }
    if (lane == 0) g_cls[row] = outc;
}

// ---------------- per-sample: som_errors, min_dist sum, BMU scatter ----------------
__global__ void persample_kernel(const float* __restrict__ X,
                                 const float* __restrict__ W,
                                 const float* __restrict__ cell_rel,
                                 float* __restrict__ out_err) {
    const int i = blockIdx.x;
    const int t = threadIdx.x;
    float4 x = *(const float4*)&X[(size_t)i * DIM + t * 4];

    float s = x.x*x.x + x.y*x.y + x.z*x.z + x.w*x.w;
    #pragma unroll
    for (int o = 16; o; o >>= 1) s += __shfl_xor_sync(0xFFFFFFFFu, s, o);
    __shared__ float red[4];
    if ((t & 31) == 0) red[t >> 5] = s;
    __syncthreads();
    float xn = red[0] + red[1] + red[2] + red[3];

    u64 pm = g_min[i];
    u64 pc = g_cls[i];
    unsigned bmu = (unsigned)pm;
    unsigned ub  = (unsigned)(pm >> 32);
    ub = (ub & 0x80000000u) ? (ub ^ 0x80000000u) : ~ub;
    float smin = __uint_as_float(ub);
    if (t == 0) atomicAdd(&g_sum, fmaxf(xn + smin, 0.0f));

    unsigned cls = (unsigned)pc;
    if (cls >= (unsigned)NCELL) cls = 0;

    float rel = cell_rel[cls] / 100.0f;
    float fac = (rel >= THR_REL) ? 0.01f * rel : 0.0f;
    float4 w = *(const float4*)&W[(size_t)cls * DIM + t * 4];
    float4 e;
    e.x = fac * (w.x - x.x);
    e.y = fac * (w.y - x.y);
    e.z = fac * (w.z - x.z);
    e.w = fac * (w.w - x.w);
    *(float4*)&out_err[(size_t)i * DIM + t * 4] = e;

    int bx = (int)(bmu / GRID), by = (int)(bmu % GRID);
    int center = by * GRID + bx;
    float* dst = &g_S0[(size_t)center * DIM + t * 4];
    atomicAdd(dst + 0, x.x);
    atomicAdd(dst + 1, x.y);
    atomicAdd(dst + 2, x.z);
    atomicAdd(dst + 3, x.w);
    if (t == 0) atomicAdd(&g_cnt[center], 1.0f);
}

// ---------------- stencil conv + SOM update ----------------
__global__ void update_kernel(const float* __restrict__ som,
                              float* __restrict__ out_som) {
    const int cell = blockIdx.x;
    const int a = cell >> 7, c = cell & 127;
    const int t = threadIdx.x;
    const int ctx = g_ctx;
    const float lr = g_lr;
    const bool flag = (g_sum / (float)BATCH) > 1e-4f;

    float denom = 0.0f;
    float4 num = make_float4(0.f, 0.f, 0.f, 0.f);
    for (int dy = -ctx; dy <= ctx; dy++) {
        int aa = a + dy;
        if (aa < 0 || aa >= GRID) continue;
        for (int dx = -ctx; dx <= ctx; dx++) {
            int cc = c + dx;
            if (cc < 0 || cc >= GRID) continue;
            int ch = max(abs(dy), abs(dx));
            float w = ldexpf(lr, -ch);
            int nb = aa * GRID + cc;
            denom += w * g_cnt[nb];
            float4 sv = *(const float4*)&g_S0[(size_t)nb * DIM + t * 4];
            num.x += w * sv.x; num.y += w * sv.y;
            num.z += w * sv.z; num.w += w * sv.w;
        }
    }
    float4 smv = *(const float4*)&som[(size_t)cell * DIM + t * 4];
    float4 o;
    if (flag) {
        o.x = smv.x + num.x - smv.x * denom;
        o.y = smv.y + num.y - smv.y * denom;
        o.z = smv.z + num.z - smv.z * denom;
        o.w = smv.w + num.w - smv.w * denom;
    } else {
        o = smv;
    }
    *(float4*)&out_som[(size_t)cell * DIM + t * 4] = o;
}

// ---------------- launch ----------------
extern "C" void kernel_launch(void* const* d_in, const int* in_sizes, int n_in,
                              void* d_out, int out_size) {
    const float* X          = (const float*)d_in[0];
    const int*   labels     = (const int*)  d_in[1];
    const float* som        = (const float*)d_in[2];
    const int*   cell_lab   = (const int*)  d_in[3];
    const float* cell_rel   = (const float*)d_in[4];
    const int*   epoch      = (const int*)  d_in[5];
    const int*   max_epochs = (const int*)  d_in[6];
    (void)in_sizes; (void)n_in; (void)out_size;

    float* out_err = (float*)d_out;
    float* out_som = (float*)d_out + (size_t)BATCH * DIM;

    cudaFuncSetAttribute(mma_argmin_kernel,
                         cudaFuncAttributeMaxDynamicSharedMemorySize, SMEMT);

    void *pS0, *pCnt, *pSum;
    cudaGetSymbolAddress(&pS0,  g_S0);
    cudaGetSymbolAddress(&pCnt, g_cnt);
    cudaGetSymbolAddress(&pSum, g_sum);
    cudaMemsetAsync(pS0,  0, sizeof(float) * (size_t)NCELL * DIM);
    cudaMemsetAsync(pCnt, 0, sizeof(float) * NCELL);
    cudaMemsetAsync(pSum, 0, sizeof(float));

    void *pxf, *pwf;
    cudaGetSymbolAddress(&pxf, g_xf);
    cudaGetSymbolAddress(&pwf, g_wf);

    schedule_kernel<<<1, 1>>>(epoch, max_epochs);
    tohalf_kernel<<<1024, 256>>>(X, (__half*)pxf, BATCH * DIM / 4);
    wprep_kernel<<<NCELL / 8, 256>>>(som, (__half*)pwf);
    mma_argmin_kernel<<<dim3(NCELL / 128, BATCH / 128), 512, SMEMT>>>(labels, cell_lab);
    reduce_rescore_kernel<<<BATCH / 8, 256>>>(X, som);
    persample_kernel<<<BATCH, 128>>>(X, som, cell_rel, out_err);
    update_kernel<<<NCELL, 128>>>(som, out_som);
}

// round 15
// speedup vs baseline: 1.0435x; 1.0130x over previous
#include <cuda_runtime.h>
#include <cuda_fp16.h>
#include <cstdint>

#define BATCH 4096
#define DIM   512
#define GRID  128
#define NCELL (GRID*GRID)   // 16384
#define THR_REL 0.95f
#define LR_MAX 0.2f
#define LR_MIN 0.05f
#define CTX_MAX 2
#define CTX_MIN 0

// GEMM tiling: CTA 128x128, 16 warps (4x4), warp 32x32, k-slab 64, 4-stage pipe
#define KC 64
#define NS (DIM/KC)          // 8 slabs
#define APITCH 144           // bytes per smem row (64 fp16 = 128B data + 16B pad)
#define ARR (128*APITCH)     // 18432 bytes per smem array
#define STG (2*ARR)          // A, B = 36864
#define HDR 1536
#define SMEMT (HDR + 4*STG)  // 148992
#define NPART 128            // one partial set per (col-tile, row)

typedef unsigned long long u64;

// ---------------- device scratch ----------------
__device__ float   g_wnorm[NCELL];
__device__ float   g_S0[NCELL * DIM];
__device__ float   g_cnt[NCELL];
__device__ float   g_sum;
__device__ float   g_lr;
__device__ int     g_ctx;
__device__ __half  g_xf[BATCH*DIM];
__device__ __half  g_wf[NCELL*DIM];
__device__ u64     g_part[(size_t)NPART * BATCH * 4];

// ---------------- PTX helpers (baseline ISA only) ----------------
__device__ __forceinline__ uint32_t smem_to_u32(const void* p) {
    uint32_t a;
    asm("{ .reg .u64 t; cvta.to.shared.u64 t, %1; cvt.u32.u64 %0, t; }" : "=r"(a) : "l"(p));
    return a;
}
#define CP_ASYNC16(d, s) \
    asm volatile("cp.async.cg.shared.global [%0], [%1], 16;" :: "r"(d), "l"(s) : "memory")
#define CP_COMMIT() asm volatile("cp.async.commit_group;" ::: "memory")
#define CP_WAIT(n)  asm volatile("cp.async.wait_group %0;" :: "n"(n) : "memory")

#define LDSM_X4(r, a) \
    asm volatile("ldmatrix.sync.aligned.m8n8.x4.shared.b16 {%0,%1,%2,%3}, [%4];" \
        : "=r"((r)[0]), "=r"((r)[1]), "=r"((r)[2]), "=r"((r)[3]) : "r"(a))
#define MMA_F16(dd, aa, bb) \
    asm volatile("mma.sync.aligned.m16n8k16.row.col.f32.f16.f16.f32 " \
        "{%0,%1,%2,%3}, {%4,%5,%6,%7}, {%8,%9}, {%0,%1,%2,%3};" \
        : "+f"((dd)[0]), "+f"((dd)[1]), "+f"((dd)[2]), "+f"((dd)[3]) \
        : "r"((aa)[0]), "r"((aa)[1]), "r"((aa)[2]), "r"((aa)[3]), \
          "r"((bb)[0]), "r"((bb)[1]))

__device__ __forceinline__ unsigned float_to_ordered(float f) {
    unsigned u = __float_as_uint(f);
    return (u & 0x80000000u) ? ~u : (u ^ 0x80000000u);
}
__device__ __forceinline__ void top2_ins(u64& m1, u64& m2, u64 v) {
    if (v < m1) { m2 = m1; m1 = v; } else if (v < m2) { m2 = v; }
}

// ---------------- schedule ----------------
__global__ void schedule_kernel(const int* __restrict__ epoch,
                                const int* __restrict__ max_epochs) {
    int e = epoch[0], me = max_epochs[0];
    float progress = (me > 0) ? (float)(me - e) / (float)me : 0.0f;
    progress = fminf(fmaxf(progress, 0.0f), 1.0f);
    float p2 = progress * progress;
    g_ctx = CTX_MIN + (int)(p2 * p2 * (float)(CTX_MAX - CTX_MIN));
    g_lr  = LR_MIN + progress * (LR_MAX - LR_MIN);
}

// ---------------- fp16 convert (X) ----------------
__global__ void tohalf_kernel(const float* __restrict__ src,
                              __half* __restrict__ dst, int n4) {
    int stride = gridDim.x * blockDim.x;
    for (int i = blockIdx.x * blockDim.x + threadIdx.x; i < n4; i += stride) {
        float4 v = ((const float4*)src)[i];
        union { __half h[4]; uint2 u; } H;
        H.h[0] = __float2half_rn(v.x);
        H.h[1] = __float2half_rn(v.y);
        H.h[2] = __float2half_rn(v.z);
        H.h[3] = __float2half_rn(v.w);
        ((uint2*)dst)[i] = H.u;
    }
}

// ---------------- fused W convert + w_norm ----------------
__global__ void wprep_kernel(const float* __restrict__ W,
                             __half* __restrict__ wf) {
    int warp = (blockIdx.x * blockDim.x + threadIdx.x) >> 5;
    int lane = threadIdx.x & 31;
    if (warp >= NCELL) return;
    const float4* row = (const float4*)(W + (size_t)warp * DIM);
    uint2* out = (uint2*)(wf + (size_t)warp * DIM);
    float s = 0.0f;
    #pragma unroll
    for (int i = 0; i < 4; i++) {
        float4 v = row[lane + 32 * i];
        s += v.x*v.x + v.y*v.y + v.z*v.z + v.w*v.w;
        union { __half h[4]; uint2 u; } H;
        H.h[0] = __float2half_rn(v.x);
        H.h[1] = __float2half_rn(v.y);
        H.h[2] = __float2half_rn(v.z);
        H.h[3] = __float2half_rn(v.w);
        out[lane + 32 * i] = H.u;
    }
    #pragma unroll
    for (int o = 16; o; o >>= 1) s += __shfl_xor_sync(0xFFFFFFFFu, s, o);
    if (lane == 0) g_wnorm[warp] = s;
}

// ---------------- fp16 mma.sync GEMM (f32 acc), 16 warps, + top-2 argmin ----------------
__global__ __launch_bounds__(512, 1)
void mma_argmin_kernel(const int* __restrict__ labels,
                       const int* __restrict__ cell_labels) {
    extern __shared__ char sm[];
    const uint32_t sbase = smem_to_u32(sm);
    const int tid = threadIdx.x;
    const int lane = tid & 31;
    const int wid = tid >> 5;
    const int rowBase = blockIdx.y * 128;
    const int colBase = blockIdx.x * 128;

    float* wn_s = (float*)sm;
    int*   cl_s = (int*)(sm + 512);
    int*   rl_s = (int*)(sm + 1024);
    if (tid < 128) {
        wn_s[tid] = g_wnorm[colBase + tid];
        cl_s[tid] = cell_labels[colBase + tid];
        rl_s[tid] = labels[rowBase + tid];
    }

    const int wm = wid >> 2;          // M group
    const int wn = wid & 3;           // N group
    const int m0  = wm * 32;
    const int n0v = wn * 32;

    float d[2][4][4];
    #pragma unroll
    for (int mi = 0; mi < 2; mi++)
        #pragma unroll
        for (int nj = 0; nj < 4; nj++)
            #pragma unroll
            for (int e = 0; e < 4; e++) d[mi][nj][e] = 0.0f;

    // ldmatrix lane-address components
    const uint32_t aOff = (uint32_t)((m0 + (lane & 15)) * APITCH + ((lane >> 4) * 8) * 2);
    const uint32_t bOff = (uint32_t)((n0v + ((lane >> 4) & 1) * 8 + (lane & 7)) * APITCH +
                                     (((lane >> 3) & 1) * 8) * 2);

    // stage loader via cp.async: A, B (4 x 16B per thread)
    auto load_stage = [&](int s) {
        const int k0 = s * KC;
        const uint32_t st = (uint32_t)HDR + (uint32_t)(s & 3) * STG;
        #pragma unroll
        for (int i = 0; i < 2; i++) {
            int slot = tid + i * 512;            // 0..1023
            int r = slot >> 3, q = slot & 7;
            uint32_t doff = sbase + st + (uint32_t)(r * APITCH + q * 16);
            CP_ASYNC16(doff,       &g_xf[(size_t)(rowBase + r) * DIM + k0 + q * 8]);
            CP_ASYNC16(doff + ARR, &g_wf[(size_t)(colBase + r) * DIM + k0 + q * 8]);
        }
    };

    auto compute_slab = [&](int s) {
        const uint32_t st = sbase + (uint32_t)HDR + (uint32_t)(s & 3) * STG;
        const uint32_t aBase = st + aOff;
        const uint32_t bBase = st + ARR + bOff;
        #pragma unroll
        for (int ks = 0; ks < KC / 16; ks++) {
            uint32_t a[2][4], bq[2][4];
            #pragma unroll
            for (int mi = 0; mi < 2; mi++)
                LDSM_X4(a[mi], aBase + (uint32_t)(mi * 16 * APITCH + ks * 32));
            #pragma unroll
            for (int p = 0; p < 2; p++)
                LDSM_X4(bq[p], bBase + (uint32_t)(p * 16 * APITCH + ks * 32));
            #pragma unroll
            for (int mi = 0; mi < 2; mi++)
                #pragma unroll
                for (int nj = 0; nj < 4; nj++)
                    MMA_F16(d[mi][nj], a[mi], &bq[nj >> 1][(nj & 1) * 2]);
        }
    };

    load_stage(0); CP_COMMIT();
    load_stage(1); CP_COMMIT();
    load_stage(2); CP_COMMIT();

    // formally correct waits: at iter s, pending-after-wait <= {s+1, s+2}
    #pragma unroll
    for (int s = 0; s < NS; s++) {
        if (s < NS - 2)      { CP_WAIT(2); }
        else if (s == NS - 2){ CP_WAIT(1); }
        else                 { CP_WAIT(0); }
        __syncthreads();
        // prefetch slab s+3 into stage (s+3)&3 == (s-1)&3 (drained by barrier above)
        if (s + 3 < NS) { load_stage(s + 3); CP_COMMIT(); }
        compute_slab(s);
    }
    __syncthreads();   // pipeline smem reads done; reuse for partials

    // ---- fused epilogue: per-row top-2 (plain + class-masked) ----
    u64* ps = (u64*)(sm + HDR);   // [row 0..127][wn 0..3][4] = 16KB
    const int g  = lane >> 2;
    const int t4 = lane & 3;
    #pragma unroll
    for (int mi = 0; mi < 2; mi++) {
        const int lr0 = m0 + mi * 16 + g;
        const int lr1 = lr0 + 8;
        const int lab0 = rl_s[lr0];
        const int lab1 = rl_s[lr1];
        u64 m1a = ~0ull, m2a = ~0ull, c1a = ~0ull, c2a = ~0ull;
        u64 m1b = ~0ull, m2b = ~0ull, c1b = ~0ull, c2b = ~0ull;
        #pragma unroll
        for (int nj = 0; nj < 4; nj++) {
            #pragma unroll
            for (int e = 0; e < 2; e++) {
                int lc = n0v + nj * 8 + t4 * 2 + e;
                float wnv = wn_s[lc];
                int   cl  = cl_s[lc];
                unsigned col = (unsigned)(colBase + lc);
                float s0 = fmaf(-2.0f, d[mi][nj][e], wnv);
                u64 p0 = ((u64)float_to_ordered(s0) << 32) | col;
                top2_ins(m1a, m2a, p0);
                if (cl == lab0) top2_ins(c1a, c2a, p0);
                float s1 = fmaf(-2.0f, d[mi][nj][2 + e], wnv);
                u64 p1 = ((u64)float_to_ordered(s1) << 32) | col;
                top2_ins(m1b, m2b, p1);
                if (cl == lab1) top2_ins(c1b, c2b, p1);
            }
        }
        #pragma unroll
        for (int o = 1; o <= 2; o <<= 1) {
            u64 q1, q2;
            q1 = __shfl_xor_sync(0xFFFFFFFFu, m1a, o); q2 = __shfl_xor_sync(0xFFFFFFFFu, m2a, o);
            top2_ins(m1a, m2a, q1); top2_ins(m1a, m2a, q2);
            q1 = __shfl_xor_sync(0xFFFFFFFFu, c1a, o); q2 = __shfl_xor_sync(0xFFFFFFFFu, c2a, o);
            top2_ins(c1a, c2a, q1); top2_ins(c1a, c2a, q2);
            q1 = __shfl_xor_sync(0xFFFFFFFFu, m1b, o); q2 = __shfl_xor_sync(0xFFFFFFFFu, m2b, o);
            top2_ins(m1b, m2b, q1); top2_ins(m1b, m2b, q2);
            q1 = __shfl_xor_sync(0xFFFFFFFFu, c1b, o); q2 = __shfl_xor_sync(0xFFFFFFFFu, c2b, o);
            top2_ins(c1b, c2b, q1); top2_ins(c1b, c2b, q2);
        }
        if (t4 == 0) {
            u64* p0 = &ps[((size_t)lr0 * 4 + wn) * 4];
            p0[0] = m1a; p0[1] = m2a; p0[2] = c1a; p0[3] = c2a;
            u64* p1 = &ps[((size_t)lr1 * 4 + wn) * 4];
            p1[0] = m1b; p1[1] = m2b; p1[2] = c1b; p1[3] = c2b;
        }
    }
    __syncthreads();

    // ---- CTA-level combine: one partial set per row ----
    if (tid < 128) {
        u64 M1 = ~0ull, M2 = ~0ull, C1 = ~0ull, C2 = ~0ull;
        #pragma unroll
        for (int w = 0; w < 4; w++) {
            const u64* p = &ps[((size_t)tid * 4 + w) * 4];
            top2_ins(M1, M2, p[0]); top2_ins(M1, M2, p[1]);
            top2_ins(C1, C2, p[2]); top2_ins(C1, C2, p[3]);
        }
        size_t pb = ((size_t)blockIdx.x * BATCH + (size_t)(rowBase + tid)) * 4;
        g_part[pb+0] = M1; g_part[pb+1] = M2; g_part[pb+2] = C1; g_part[pb+3] = C2;
    }
}

// ---------------- fused merge + exact fp32 rescore + per-sample outputs ----------------
__device__ __forceinline__ float warp_dot(const float* __restrict__ x,
                                          const float* __restrict__ w, int lane) {
    const float4* xv = (const float4*)x + lane * 4;
    const float4* wv = (const float4*)w + lane * 4;
    float acc = 0.0f;
    #pragma unroll
    for (int q = 0; q < 4; q++) {
        float4 a = xv[q], b = wv[q];
        acc = fmaf(a.x, b.x, acc); acc = fmaf(a.y, b.y, acc);
        acc = fmaf(a.z, b.z, acc); acc = fmaf(a.w, b.w, acc);
    }
    #pragma unroll
    for (int o = 16; o; o >>= 1) acc += __shfl_xor_sync(0xFFFFFFFFu, acc, o);
    return acc;
}

__global__ void persample_kernel(const float* __restrict__ X,
                                 const float* __restrict__ W,
                                 const float* __restrict__ cell_rel,
                                 float* __restrict__ out_err) {
    const int i = blockIdx.x;
    const int t = threadIdx.x;
    const int lane = t & 31;
    float4 x = *(const float4*)&X[(size_t)i * DIM + t * 4];

    float s = x.x*x.x + x.y*x.y + x.z*x.z + x.w*x.w;
    #pragma unroll
    for (int o = 16; o; o >>= 1) s += __shfl_xor_sync(0xFFFFFFFFu, s, o);
    __shared__ float red[4];
    __shared__ u64 sh_pm, sh_pc;
    if ((t & 31) == 0) red[t >> 5] = s;
    __syncthreads();
    float xn = red[0] + red[1] + red[2] + red[3];

    // ---- warp 0: merge 128 tile-partials + exact fp32 rescore (R10 semantics) ----
    if (t < 32) {
        u64 m1 = ~0ull, m2 = ~0ull, c1 = ~0ull, c2 = ~0ull;
        #pragma unroll
        for (int tt = 0; tt < NPART / 32; tt++) {
            int tile = lane + tt * 32;
            const ulonglong2* p = (const ulonglong2*)&g_part[((size_t)tile * BATCH + i) * 4];
            ulonglong2 a = p[0], b = p[1];
            top2_ins(m1, m2, a.x); top2_ins(m1, m2, a.y);
            top2_ins(c1, c2, b.x); top2_ins(c1, c2, b.y);
        }
        #pragma unroll
        for (int o = 16; o; o >>= 1) {
            u64 q1 = __shfl_xor_sync(0xFFFFFFFFu, m1, o);
            u64 q2 = __shfl_xor_sync(0xFFFFFFFFu, m2, o);
            top2_ins(m1, m2, q1); top2_ins(m1, m2, q2);
            q1 = __shfl_xor_sync(0xFFFFFFFFu, c1, o);
            q2 = __shfl_xor_sync(0xFFFFFFFFu, c2, o);
            top2_ins(c1, c2, q1); top2_ins(c1, c2, q2);
        }

        const float* xr = X + (size_t)i * DIM;

        unsigned i1 = (unsigned)m1, i2 = (unsigned)m2;
        float s1 = g_wnorm[i1] - 2.0f * warp_dot(xr, W + (size_t)i1 * DIM, lane);
        float s2 = g_wnorm[i2] - 2.0f * warp_dot(xr, W + (size_t)i2 * DIM, lane);
        unsigned best = i1; float sb = s1;
        if (s2 < sb || (s2 == sb && i2 < best)) { best = i2; sb = s2; }
        if (lane == 0)
            sh_pm = ((u64)float_to_ordered(sb) << 32) | best;

        u64 outc = ~0ull;
        if (c1 != ~0ull) {
            unsigned j1 = (unsigned)c1;
            float t1 = g_wnorm[j1] - 2.0f * warp_dot(xr, W + (size_t)j1 * DIM, lane);
            unsigned bc = j1; float tb = t1;
            if (c2 != ~0ull) {
                unsigned j2 = (unsigned)c2;
                float t2 = g_wnorm[j2] - 2.0f * warp_dot(xr, W + (size_t)j2 * DIM, lane);
                if (t2 < tb || (t2 == tb && j2 < bc)) { bc = j2; tb = t2; }
            }
            outc = ((u64)float_to_ordered(tb) << 32) | bc;
        }
        if (lane == 0) sh_pc = outc;
    }
    __syncthreads();

    u64 pm = sh_pm;
    u64 pc = sh_pc;
    unsigned bmu = (unsigned)pm;
    unsigned ub  = (unsigned)(pm >> 32);
    ub = (ub & 0x80000000u) ? (ub ^ 0x80000000u) : ~ub;
    float smin = __uint_as_float(ub);
    if (t == 0) atomicAdd(&g_sum, fmaxf(xn + smin, 0.0f));

    unsigned cls = (unsigned)pc;
    if (cls >= (unsigned)NCELL) cls = 0;

    float rel = cell_rel[cls] / 100.0f;
    float fac = (rel >= THR_REL) ? 0.01f * rel : 0.0f;
    float4 w = *(const float4*)&W[(size_t)cls * DIM + t * 4];
    float4 e;
    e.x = fac * (w.x - x.x);
    e.y = fac * (w.y - x.y);
    e.z = fac * (w.z - x.z);
    e.w = fac * (w.w - x.w);
    *(float4*)&out_err[(size_t)i * DIM + t * 4] = e;

    int bx = (int)(bmu / GRID), by = (int)(bmu % GRID);
    int center = by * GRID + bx;
    float* dst = &g_S0[(size_t)center * DIM + t * 4];
    atomicAdd(dst + 0, x.x);
    atomicAdd(dst + 1, x.y);
    atomicAdd(dst + 2, x.z);
    atomicAdd(dst + 3, x.w);
    if (t == 0) atomicAdd(&g_cnt[center], 1.0f);
}

// ---------------- stencil conv + SOM update ----------------
__global__ void update_kernel(const float* __restrict__ som,
                              float* __restrict__ out_som) {
    const int cell = blockIdx.x;
    const int a = cell >> 7, c = cell & 127;
    const int t = threadIdx.x;
    const int ctx = g_ctx;
    const float lr = g_lr;
    const bool flag = (g_sum / (float)BATCH) > 1e-4f;

    float denom = 0.0f;
    float4 num = make_float4(0.f, 0.f, 0.f, 0.f);
    for (int dy = -ctx; dy <= ctx; dy++) {
        int aa = a + dy;
        if (aa < 0 || aa >= GRID) continue;
        for (int dx = -ctx; dx <= ctx; dx++) {
            int cc = c + dx;
            if (cc < 0 || cc >= GRID) continue;
            int ch = max(abs(dy), abs(dx));
            float w = ldexpf(lr, -ch);
            int nb = aa * GRID + cc;
            denom += w * g_cnt[nb];
            float4 sv = *(const float4*)&g_S0[(size_t)nb * DIM + t * 4];
            num.x += w * sv.x; num.y += w * sv.y;
            num.z += w * sv.z; num.w += w * sv.w;
        }
    }
    float4 smv = *(const float4*)&som[(size_t)cell * DIM + t * 4];
    float4 o;
    if (flag) {
        o.x = smv.x + num.x - smv.x * denom;
        o.y = smv.y + num.y - smv.y * denom;
        o.z = smv.z + num.z - smv.z * denom;
        o.w = smv.w + num.w - smv.w * denom;
    } else {
        o = smv;
    }
    *(float4*)&out_som[(size_t)cell * DIM + t * 4] = o;
}

// ---------------- launch ----------------
extern "C" void kernel_launch(void* const* d_in, const int* in_sizes, int n_in,
                              void* d_out, int out_size) {
    const float* X          = (const float*)d_in[0];
    const int*   labels     = (const int*)  d_in[1];
    const float* som        = (const float*)d_in[2];
    const int*   cell_lab   = (const int*)  d_in[3];
    const float* cell_rel   = (const float*)d_in[4];
    const int*   epoch      = (const int*)  d_in[5];
    const int*   max_epochs = (const int*)  d_in[6];
    (void)in_sizes; (void)n_in; (void)out_size;

    float* out_err = (float*)d_out;
    float* out_som = (float*)d_out + (size_t)BATCH * DIM;

    cudaFuncSetAttribute(mma_argmin_kernel,
                         cudaFuncAttributeMaxDynamicSharedMemorySize, SMEMT);

    void *pS0, *pCnt, *pSum;
    cudaGetSymbolAddress(&pS0,  g_S0);
    cudaGetSymbolAddress(&pCnt, g_cnt);
    cudaGetSymbolAddress(&pSum, g_sum);
    cudaMemsetAsync(pS0,  0, sizeof(float) * (size_t)NCELL * DIM);
    cudaMemsetAsync(pCnt, 0, sizeof(float) * NCELL);
    cudaMemsetAsync(pSum, 0, sizeof(float));

    void *pxf, *pwf;
    cudaGetSymbolAddress(&pxf, g_xf);
    cudaGetSymbolAddress(&pwf, g_wf);

    schedule_kernel<<<1, 1>>>(epoch, max_epochs);
    tohalf_kernel<<<1024, 256>>>(X, (__half*)pxf, BATCH * DIM / 4);
    wprep_kernel<<<NCELL / 8, 256>>>(som, (__half*)pwf);
    mma_argmin_kernel<<<dim3(NCELL / 128, BATCH / 128), 512, SMEMT>>>(labels, cell_lab);
    persample_kernel<<<BATCH, 128>>>(X, som, cell_rel, out_err);
    update_kernel<<<NCELL, 128>>>(som, out_som);
}

// round 16
// speedup vs baseline: 1.0664x; 1.0220x over previous
#include <cuda_runtime.h>
#include <cuda_fp16.h>
#include <cstdint>

#define BATCH 4096
#define DIM   512
#define GRID  128
#define NCELL (GRID*GRID)   // 16384
#define THR_REL 0.95f
#define LR_MAX 0.2f
#define LR_MIN 0.05f
#define CTX_MAX 2
#define CTX_MIN 0

// GEMM tiling: CTA 128x128, 8 warps (2x4), warp 64x32, k-slab 64, 4-stage pipe
#define KC 64
#define NS (DIM/KC)          // 8 slabs
#define APITCH 144           // bytes per smem row (64 fp16 = 128B data + 16B pad)
#define ARR (128*APITCH)     // 18432 bytes per smem array
#define STG (2*ARR)          // A, B = 36864
#define HDR 1536
#define SMEMT (HDR + 4*STG)  // 148992
#define NPART 128            // one partial set per (col-tile, row)

typedef unsigned long long u64;

// ---------------- device scratch ----------------
__device__ float   g_wnorm[NCELL];
__device__ float   g_S0[NCELL * DIM];
__device__ float   g_cnt[NCELL];
__device__ float   g_sum;
__device__ float   g_lr;
__device__ int     g_ctx;
__device__ __half  g_xf[BATCH*DIM];
__device__ __half  g_wf[NCELL*DIM];
__device__ u64     g_part[(size_t)NPART * BATCH * 4];

// ---------------- PTX helpers (baseline ISA only) ----------------
__device__ __forceinline__ uint32_t smem_to_u32(const void* p) {
    uint32_t a;
    asm("{ .reg .u64 t; cvta.to.shared.u64 t, %1; cvt.u32.u64 %0, t; }" : "=r"(a) : "l"(p));
    return a;
}
#define CP_ASYNC16(d, s) \
    asm volatile("cp.async.cg.shared.global [%0], [%1], 16;" :: "r"(d), "l"(s) : "memory")
#define CP_COMMIT() asm volatile("cp.async.commit_group;" ::: "memory")
#define CP_WAIT(n)  asm volatile("cp.async.wait_group %0;" :: "n"(n) : "memory")

#define LDSM_X4(r, a) \
    asm volatile("ldmatrix.sync.aligned.m8n8.x4.shared.b16 {%0,%1,%2,%3}, [%4];" \
        : "=r"((r)[0]), "=r"((r)[1]), "=r"((r)[2]), "=r"((r)[3]) : "r"(a))
#define MMA_F16(dd, aa, bb) \
    asm volatile("mma.sync.aligned.m16n8k16.row.col.f32.f16.f16.f32 " \
        "{%0,%1,%2,%3}, {%4,%5,%6,%7}, {%8,%9}, {%0,%1,%2,%3};" \
        : "+f"((dd)[0]), "+f"((dd)[1]), "+f"((dd)[2]), "+f"((dd)[3]) \
        : "r"((aa)[0]), "r"((aa)[1]), "r"((aa)[2]), "r"((aa)[3]), \
          "r"((bb)[0]), "r"((bb)[1]))

__device__ __forceinline__ unsigned float_to_ordered(float f) {
    unsigned u = __float_as_uint(f);
    return (u & 0x80000000u) ? ~u : (u ^ 0x80000000u);
}
__device__ __forceinline__ void top2_ins(u64& m1, u64& m2, u64 v) {
    if (v < m1) { m2 = m1; m1 = v; } else if (v < m2) { m2 = v; }
}

// ---------------- schedule ----------------
__global__ void schedule_kernel(const int* __restrict__ epoch,
                                const int* __restrict__ max_epochs) {
    int e = epoch[0], me = max_epochs[0];
    float progress = (me > 0) ? (float)(me - e) / (float)me : 0.0f;
    progress = fminf(fmaxf(progress, 0.0f), 1.0f);
    float p2 = progress * progress;
    g_ctx = CTX_MIN + (int)(p2 * p2 * (float)(CTX_MAX - CTX_MIN));
    g_lr  = LR_MIN + progress * (LR_MAX - LR_MIN);
}

// ---------------- fp16 convert (X) ----------------
__global__ void tohalf_kernel(const float* __restrict__ src,
                              __half* __restrict__ dst, int n4) {
    int stride = gridDim.x * blockDim.x;
    for (int i = blockIdx.x * blockDim.x + threadIdx.x; i < n4; i += stride) {
        float4 v = ((const float4*)src)[i];
        union { __half h[4]; uint2 u; } H;
        H.h[0] = __float2half_rn(v.x);
        H.h[1] = __float2half_rn(v.y);
        H.h[2] = __float2half_rn(v.z);
        H.h[3] = __float2half_rn(v.w);
        ((uint2*)dst)[i] = H.u;
    }
}

// ---------------- fused W convert + w_norm ----------------
__global__ void wprep_kernel(const float* __restrict__ W,
                             __half* __restrict__ wf) {
    int warp = (blockIdx.x * blockDim.x + threadIdx.x) >> 5;
    int lane = threadIdx.x & 31;
    if (warp >= NCELL) return;
    const float4* row = (const float4*)(W + (size_t)warp * DIM);
    uint2* out = (uint2*)(wf + (size_t)warp * DIM);
    float s = 0.0f;
    #pragma unroll
    for (int i = 0; i < 4; i++) {
        float4 v = row[lane + 32 * i];
        s += v.x*v.x + v.y*v.y + v.z*v.z + v.w*v.w;
        union { __half h[4]; uint2 u; } H;
        H.h[0] = __float2half_rn(v.x);
        H.h[1] = __float2half_rn(v.y);
        H.h[2] = __float2half_rn(v.z);
        H.h[3] = __float2half_rn(v.w);
        out[lane + 32 * i] = H.u;
    }
    #pragma unroll
    for (int o = 16; o; o >>= 1) s += __shfl_xor_sync(0xFFFFFFFFu, s, o);
    if (lane == 0) g_wnorm[warp] = s;
}

// ---------------- fp16 mma.sync GEMM, 8 warps (64x32), frag double-buffer ----------------
__global__ __launch_bounds__(256, 1)
void mma_argmin_kernel(const int* __restrict__ labels,
                       const int* __restrict__ cell_labels) {
    extern __shared__ char sm[];
    const uint32_t sbase = smem_to_u32(sm);
    const int tid = threadIdx.x;
    const int lane = tid & 31;
    const int wid = tid >> 5;
    const int rowBase = blockIdx.y * 128;
    const int colBase = blockIdx.x * 128;

    float* wn_s = (float*)sm;
    int*   cl_s = (int*)(sm + 512);
    int*   rl_s = (int*)(sm + 1024);
    if (tid < 128) {
        wn_s[tid] = g_wnorm[colBase + tid];
        cl_s[tid] = cell_labels[colBase + tid];
        rl_s[tid] = labels[rowBase + tid];
    }

    const int wm = wid >> 2;          // 0..1 (M group, 64 rows)
    const int wc = wid & 3;           // 0..3 (N group, 32 cols)
    const int m0  = wm * 64;
    const int n0v = wc * 32;

    float d[4][4][4];
    #pragma unroll
    for (int mi = 0; mi < 4; mi++)
        #pragma unroll
        for (int nj = 0; nj < 4; nj++)
            #pragma unroll
            for (int e = 0; e < 4; e++) d[mi][nj][e] = 0.0f;

    // ldmatrix lane-address components
    const uint32_t aOff = (uint32_t)((m0 + (lane & 15)) * APITCH + ((lane >> 4) * 8) * 2);
    const uint32_t bOff = (uint32_t)((n0v + ((lane >> 4) & 1) * 8 + (lane & 7)) * APITCH +
                                     (((lane >> 3) & 1) * 8) * 2);

    // stage loader via cp.async: A, B (8 x 16B per thread)
    auto load_stage = [&](int s) {
        const int k0 = s * KC;
        const uint32_t st = (uint32_t)HDR + (uint32_t)(s & 3) * STG;
        #pragma unroll
        for (int i = 0; i < 4; i++) {
            int slot = tid + i * 256;            // 0..1023
            int r = slot >> 3, q = slot & 7;
            uint32_t doff = sbase + st + (uint32_t)(r * APITCH + q * 16);
            CP_ASYNC16(doff,       &g_xf[(size_t)(rowBase + r) * DIM + k0 + q * 8]);
            CP_ASYNC16(doff + ARR, &g_wf[(size_t)(colBase + r) * DIM + k0 + q * 8]);
        }
    };

    // ping-pong fragment buffers
    uint32_t af[2][4][4], bf[2][2][4];

    load_stage(0); CP_COMMIT();
    load_stage(1); CP_COMMIT();
    load_stage(2); CP_COMMIT();

    #pragma unroll
    for (int s = 0; s < NS; s++) {
        if (s < NS - 2)       { CP_WAIT(2); }
        else if (s == NS - 2) { CP_WAIT(1); }
        else                  { CP_WAIT(0); }
        __syncthreads();
        // prefetch slab s+3 into stage (s+3)&3 == (s-1)&3 (drained by barrier above)
        if (s + 3 < NS) { load_stage(s + 3); CP_COMMIT(); }

        const uint32_t st = sbase + (uint32_t)HDR + (uint32_t)(s & 3) * STG;
        const uint32_t aBase = st + aOff;
        const uint32_t bBase = st + ARR + bOff;

        // preload ks=0 fragments
        #pragma unroll
        for (int mi = 0; mi < 4; mi++)
            LDSM_X4(af[0][mi], aBase + (uint32_t)(mi * 16 * APITCH));
        #pragma unroll
        for (int p = 0; p < 2; p++)
            LDSM_X4(bf[0][p], bBase + (uint32_t)(p * 16 * APITCH));

        #pragma unroll
        for (int ks = 0; ks < KC / 16; ks++) {
            const int cur = ks & 1;
            const int nxt = cur ^ 1;
            if (ks + 1 < KC / 16) {
                #pragma unroll
                for (int mi = 0; mi < 4; mi++)
                    LDSM_X4(af[nxt][mi], aBase + (uint32_t)(mi * 16 * APITCH + (ks + 1) * 32));
                #pragma unroll
                for (int p = 0; p < 2; p++)
                    LDSM_X4(bf[nxt][p], bBase + (uint32_t)(p * 16 * APITCH + (ks + 1) * 32));
            }
            #pragma unroll
            for (int mi = 0; mi < 4; mi++)
                #pragma unroll
                for (int nj = 0; nj < 4; nj++)
                    MMA_F16(d[mi][nj], af[cur][mi], &bf[cur][nj >> 1][(nj & 1) * 2]);
        }
    }
    __syncthreads();   // pipeline smem reads done; reuse for partials

    // ---- fused epilogue: per-row top-2 (plain + class-masked) ----
    u64* ps = (u64*)(sm + HDR);   // [row 0..127][wc 0..3][4] = 16KB
    const int g  = lane >> 2;
    const int t4 = lane & 3;
    #pragma unroll
    for (int mi = 0; mi < 4; mi++) {
        const int lr0 = m0 + mi * 16 + g;
        const int lr1 = lr0 + 8;
        const int lab0 = rl_s[lr0];
        const int lab1 = rl_s[lr1];
        u64 m1a = ~0ull, m2a = ~0ull, c1a = ~0ull, c2a = ~0ull;
        u64 m1b = ~0ull, m2b = ~0ull, c1b = ~0ull, c2b = ~0ull;
        #pragma unroll
        for (int nj = 0; nj < 4; nj++) {
            #pragma unroll
            for (int e = 0; e < 2; e++) {
                int lc = n0v + nj * 8 + t4 * 2 + e;
                float wnv = wn_s[lc];
                int   cl  = cl_s[lc];
                unsigned col = (unsigned)(colBase + lc);
                float s0 = fmaf(-2.0f, d[mi][nj][e], wnv);
                u64 p0 = ((u64)float_to_ordered(s0) << 32) | col;
                top2_ins(m1a, m2a, p0);
                if (cl == lab0) top2_ins(c1a, c2a, p0);
                float s1 = fmaf(-2.0f, d[mi][nj][2 + e], wnv);
                u64 p1 = ((u64)float_to_ordered(s1) << 32) | col;
                top2_ins(m1b, m2b, p1);
                if (cl == lab1) top2_ins(c1b, c2b, p1);
            }
        }
        #pragma unroll
        for (int o = 1; o <= 2; o <<= 1) {
            u64 q1, q2;
            q1 = __shfl_xor_sync(0xFFFFFFFFu, m1a, o); q2 = __shfl_xor_sync(0xFFFFFFFFu, m2a, o);
            top2_ins(m1a, m2a, q1); top2_ins(m1a, m2a, q2);
            q1 = __shfl_xor_sync(0xFFFFFFFFu, c1a, o); q2 = __shfl_xor_sync(0xFFFFFFFFu, c2a, o);
            top2_ins(c1a, c2a, q1); top2_ins(c1a, c2a, q2);
            q1 = __shfl_xor_sync(0xFFFFFFFFu, m1b, o); q2 = __shfl_xor_sync(0xFFFFFFFFu, m2b, o);
            top2_ins(m1b, m2b, q1); top2_ins(m1b, m2b, q2);
            q1 = __shfl_xor_sync(0xFFFFFFFFu, c1b, o); q2 = __shfl_xor_sync(0xFFFFFFFFu, c2b, o);
            top2_ins(c1b, c2b, q1); top2_ins(c1b, c2b, q2);
        }
        if (t4 == 0) {
            u64* p0 = &ps[((size_t)lr0 * 4 + wc) * 4];
            p0[0] = m1a; p0[1] = m2a; p0[2] = c1a; p0[3] = c2a;
            u64* p1 = &ps[((size_t)lr1 * 4 + wc) * 4];
            p1[0] = m1b; p1[1] = m2b; p1[2] = c1b; p1[3] = c2b;
        }
    }
    __syncthreads();

    // ---- CTA-level combine: one partial set per row ----
    if (tid < 128) {
        u64 M1 = ~0ull, M2 = ~0ull, C1 = ~0ull, C2 = ~0ull;
        #pragma unroll
        for (int w = 0; w < 4; w++) {
            const u64* p = &ps[((size_t)tid * 4 + w) * 4];
            top2_ins(M1, M2, p[0]); top2_ins(M1, M2, p[1]);
            top2_ins(C1, C2, p[2]); top2_ins(C1, C2, p[3]);
        }
        size_t pb = ((size_t)blockIdx.x * BATCH + (size_t)(rowBase + tid)) * 4;
        g_part[pb+0] = M1; g_part[pb+1] = M2; g_part[pb+2] = C1; g_part[pb+3] = C2;
    }
}

// ---------------- fused merge + exact fp32 rescore + per-sample outputs ----------------
__device__ __forceinline__ float warp_dot(const float* __restrict__ x,
                                          const float* __restrict__ w, int lane) {
    const float4* xv = (const float4*)x + lane * 4;
    const float4* wv = (const float4*)w + lane * 4;
    float acc = 0.0f;
    #pragma unroll
    for (int q = 0; q < 4; q++) {
        float4 a = xv[q], b = wv[q];
        acc = fmaf(a.x, b.x, acc); acc = fmaf(a.y, b.y, acc);
        acc = fmaf(a.z, b.z, acc); acc = fmaf(a.w, b.w, acc);
    }
    #pragma unroll
    for (int o = 16; o; o >>= 1) acc += __shfl_xor_sync(0xFFFFFFFFu, acc, o);
    return acc;
}

__global__ void persample_kernel(const float* __restrict__ X,
                                 const float* __restrict__ W,
                                 const float* __restrict__ cell_rel,
                                 float* __restrict__ out_err) {
    const int i = blockIdx.x;
    const int t = threadIdx.x;
    const int lane = t & 31;
    float4 x = *(const float4*)&X[(size_t)i * DIM + t * 4];

    float s = x.x*x.x + x.y*x.y + x.z*x.z + x.w*x.w;
    #pragma unroll
    for (int o = 16; o; o >>= 1) s += __shfl_xor_sync(0xFFFFFFFFu, s, o);
    __shared__ float red[4];
    __shared__ u64 sh_pm, sh_pc;
    if ((t & 31) == 0) red[t >> 5] = s;
    __syncthreads();
    float xn = red[0] + red[1] + red[2] + red[3];

    // ---- warp 0: merge 128 tile-partials + exact fp32 rescore ----
    if (t < 32) {
        u64 m1 = ~0ull, m2 = ~0ull, c1 = ~0ull, c2 = ~0ull;
        #pragma unroll
        for (int tt = 0; tt < NPART / 32; tt++) {
            int tile = lane + tt * 32;
            const ulonglong2* p = (const ulonglong2*)&g_part[((size_t)tile * BATCH + i) * 4];
            ulonglong2 a = p[0], b = p[1];
            top2_ins(m1, m2, a.x); top2_ins(m1, m2, a.y);
            top2_ins(c1, c2, b.x); top2_ins(c1, c2, b.y);
        }
        #pragma unroll
        for (int o = 16; o; o >>= 1) {
            u64 q1 = __shfl_xor_sync(0xFFFFFFFFu, m1, o);
            u64 q2 = __shfl_xor_sync(0xFFFFFFFFu, m2, o);
            top2_ins(m1, m2, q1); top2_ins(m1, m2, q2);
            q1 = __shfl_xor_sync(0xFFFFFFFFu, c1, o);
            q2 = __shfl_xor_sync(0xFFFFFFFFu, c2, o);
            top2_ins(c1, c2, q1); top2_ins(c1, c2, q2);
        }

        const float* xr = X + (size_t)i * DIM;

        unsigned i1 = (unsigned)m1, i2 = (unsigned)m2;
        float s1 = g_wnorm[i1] - 2.0f * warp_dot(xr, W + (size_t)i1 * DIM, lane);
        float s2 = g_wnorm[i2] - 2.0f * warp_dot(xr, W + (size_t)i2 * DIM, lane);
        unsigned best = i1; float sb = s1;
        if (s2 < sb || (s2 == sb && i2 < best)) { best = i2; sb = s2; }
        if (lane == 0)
            sh_pm = ((u64)float_to_ordered(sb) << 32) | best;

        u64 outc = ~0ull;
        if (c1 != ~0ull) {
            unsigned j1 = (unsigned)c1;
            float t1 = g_wnorm[j1] - 2.0f * warp_dot(xr, W + (size_t)j1 * DIM, lane);
            unsigned bc = j1; float tb = t1;
            if (c2 != ~0ull) {
                unsigned j2 = (unsigned)c2;
                float t2 = g_wnorm[j2] - 2.0f * warp_dot(xr, W + (size_t)j2 * DIM, lane);
                if (t2 < tb || (t2 == tb && j2 < bc)) { bc = j2; tb = t2; }
            }
            outc = ((u64)float_to_ordered(tb) << 32) | bc;
        }
        if (lane == 0) sh_pc = outc;
    }
    __syncthreads();

    u64 pm = sh_pm;
    u64 pc = sh_pc;
    unsigned bmu = (unsigned)pm;
    unsigned ub  = (unsigned)(pm >> 32);
    ub = (ub & 0x80000000u) ? (ub ^ 0x80000000u) : ~ub;
    float smin = __uint_as_float(ub);
    if (t == 0) atomicAdd(&g_sum, fmaxf(xn + smin, 0.0f));

    unsigned cls = (unsigned)pc;
    if (cls >= (unsigned)NCELL) cls = 0;

    float rel = cell_rel[cls] / 100.0f;
    float fac = (rel >= THR_REL) ? 0.01f * rel : 0.0f;
    float4 w = *(const float4*)&W[(size_t)cls * DIM + t * 4];
    float4 e;
    e.x = fac * (w.x - x.x);
    e.y = fac * (w.y - x.y);
    e.z = fac * (w.z - x.z);
    e.w = fac * (w.w - x.w);
    *(float4*)&out_err[(size_t)i * DIM + t * 4] = e;

    int bx = (int)(bmu / GRID), by = (int)(bmu % GRID);
    int center = by * GRID + bx;
    float* dst = &g_S0[(size_t)center * DIM + t * 4];
    atomicAdd(dst + 0, x.x);
    atomicAdd(dst + 1, x.y);
    atomicAdd(dst + 2, x.z);
    atomicAdd(dst + 3, x.w);
    if (t == 0) atomicAdd(&g_cnt[center], 1.0f);
}

// ---------------- stencil conv + SOM update ----------------
__global__ void update_kernel(const float* __restrict__ som,
                              float* __restrict__ out_som) {
    const int cell = blockIdx.x;
    const int a = cell >> 7, c = cell & 127;
    const int t = threadIdx.x;
    const int ctx = g_ctx;
    const float lr = g_lr;
    const bool flag = (g_sum / (float)BATCH) > 1e-4f;

    float denom = 0.0f;
    float4 num = make_float4(0.f, 0.f, 0.f, 0.f);
    for (int dy = -ctx; dy <= ctx; dy++) {
        int aa = a + dy;
        if (aa < 0 || aa >= GRID) continue;
        for (int dx = -ctx; dx <= ctx; dx++) {
            int cc = c + dx;
            if (cc < 0 || cc >= GRID) continue;
            int ch = max(abs(dy), abs(dx));
            float w = ldexpf(lr, -ch);
            int nb = aa * GRID + cc;
            denom += w * g_cnt[nb];
            float4 sv = *(const float4*)&g_S0[(size_t)nb * DIM + t * 4];
            num.x += w * sv.x; num.y += w * sv.y;
            num.z += w * sv.z; num.w += w * sv.w;
        }
    }
    float4 smv = *(const float4*)&som[(size_t)cell * DIM + t * 4];
    float4 o;
    if (flag) {
        o.x = smv.x + num.x - smv.x * denom;
        o.y = smv.y + num.y - smv.y * denom;
        o.z = smv.z + num.z - smv.z * denom;
        o.w = smv.w + num.w - smv.w * denom;
    } else {
        o = smv;
    }
    *(float4*)&out_som[(size_t)cell * DIM + t * 4] = o;
}

// ---------------- launch ----------------
extern "C" void kernel_launch(void* const* d_in, const int* in_sizes, int n_in,
                              void* d_out, int out_size) {
    const float* X          = (const float*)d_in[0];
    const int*   labels     = (const int*)  d_in[1];
    const float* som        = (const float*)d_in[2];
    const int*   cell_lab   = (const int*)  d_in[3];
    const float* cell_rel   = (const float*)d_in[4];
    const int*   epoch      = (const int*)  d_in[5];
    const int*   max_epochs = (const int*)  d_in[6];
    (void)in_sizes; (void)n_in; (void)out_size;

    float* out_err = (float*)d_out;
    float* out_som = (float*)d_out + (size_t)BATCH * DIM;

    cudaFuncSetAttribute(mma_argmin_kernel,
                         cudaFuncAttributeMaxDynamicSharedMemorySize, SMEMT);

    void *pS0, *pCnt, *pSum;
    cudaGetSymbolAddress(&pS0,  g_S0);
    cudaGetSymbolAddress(&pCnt, g_cnt);
    cudaGetSymbolAddress(&pSum, g_sum);
    cudaMemsetAsync(pS0,  0, sizeof(float) * (size_t)NCELL * DIM);
    cudaMemsetAsync(pCnt, 0, sizeof(float) * NCELL);
    cudaMemsetAsync(pSum, 0, sizeof(float));

    void *pxf, *pwf;
    cudaGetSymbolAddress(&pxf, g_xf);
    cudaGetSymbolAddress(&pwf, g_wf);

    schedule_kernel<<<1, 1>>>(epoch, max_epochs);
    tohalf_kernel<<<1024, 256>>>(X, (__half*)pxf, BATCH * DIM / 4);
    wprep_kernel<<<NCELL / 8, 256>>>(som, (__half*)pwf);
    mma_argmin_kernel<<<dim3(NCELL / 128, BATCH / 128), 256, SMEMT>>>(labels, cell_lab);
    persample_kernel<<<BATCH, 128>>>(X, som, cell_rel, out_err);
    update_kernel<<<NCELL, 128>>>(som, out_som);
}